// round 16
// baseline (speedup 1.0000x reference)
#include <cuda_runtime.h>

#define BB 16
#define CC 64
#define HH 192
#define WW 192
#define HT 64   // pooled spatial size

// -------------------------------------------------------------------------
// Megakernel: one block per (b,c) plane, 256 threads.
//  phase 1: fused maxpool3x3(s1,p1) + blurpool(4x4,s3,reflect(1,2))
//           -> xtem*64 (64x64) in smem (8 chunks of 8 output rows)
//  phase 2: combined 87-tap stencil + BN(+1/64 fold) + sigmoid -> gate
//           single 16-row pass, weight-register formulation (low live set)
//  phase 3: out = x * gate[i/3, j/3], coalesced float4 stream (6-wide MLP)
// -------------------------------------------------------------------------
__global__ void __launch_bounds__(256) k_mega(
        const float* __restrict__ x,
        const float* __restrict__ wh1, const float* __restrict__ wv1,
        const float* __restrict__ wh2, const float* __restrict__ wv2,
        const float* __restrict__ gamma, const float* __restrict__ beta,
        const float* __restrict__ mean,  const float* __restrict__ var,
        float* __restrict__ out) {
    __shared__ float bufA[6336];   // pool: vm[25][192] @0, cb[8][192] @4800
                                   // att:  tile 76x80 @0
    __shared__ float bufB[4096];   // xtem 64x64, then gate 64x64
    __shared__ float wc[169];      // combined 13x13 stencil

    int plane = blockIdx.x;
    int ch    = plane % CC;
    int tid   = threadIdx.x;
    const float* xp = x + (size_t)plane * (HH*WW);

    // ---- build combined stencil (disjoint scatter per phase) ----
    if (tid < 169) wc[tid] = 0.f;
    __syncthreads();
    if (tid < 33) { int a = tid/3  - 5, b = tid%3  - 1; wc[(a+6)*13 + (b+6)]   += wh1[ch*33 + tid]; }
    __syncthreads();
    if (tid < 33) { int a = tid/11 - 1, b = tid%11 - 5; wc[(a+6)*13 + (b+6)]   += wv1[ch*33 + tid]; }
    __syncthreads();
    if (tid < 33) { int a = tid/3  - 5, b = tid%3  - 1; wc[(a+6)*13 + (b-a+6)] += wh2[ch*33 + tid]; }
    __syncthreads();
    if (tid < 33) { int s = tid/11 - 1, t = tid%11 - 5; wc[(s-t+6)*13 + (t+6)] += wv2[ch*33 + tid]; }

    // ================= phase 1: pool -> bufB (xtem * 64) =================
    {
        float* vm = bufA;            // [25][192]
        float* cb = bufA + 4800;     // [8][192]
        int q  = tid % 48;           // column quad
        int ry = tid / 48;           // 0..5 (active when <5)
        bool act = (tid < 240);

        for (int chunk = 0; chunk < 8; chunk++) {
            int oh0    = chunk * 8;
            int prbase = 3*oh0 - 1;

            // stage 1: rolling vertical 3-max, vm rows ry*5..ry*5+4
            if (act) {
                int base = prbase + ry*5;
                int ra = min(max(base-1, 0), 191);
                int rb = min(max(base,   0), 191);
                float4 r0 = __ldg((const float4*)(xp + (size_t)ra*WW) + q);
                float4 r1 = __ldg((const float4*)(xp + (size_t)rb*WW) + q);
                #pragma unroll
                for (int k = 0; k < 5; k++) {
                    int rc = min(max(base+k+1, 0), 191);
                    float4 r2 = __ldg((const float4*)(xp + (size_t)rc*WW) + q);
                    float4 m;
                    m.x = fmaxf(fmaxf(r0.x, r1.x), r2.x);
                    m.y = fmaxf(fmaxf(r0.y, r1.y), r2.y);
                    m.z = fmaxf(fmaxf(r0.z, r1.z), r2.z);
                    m.w = fmaxf(fmaxf(r0.w, r1.w), r2.w);
                    *((float4*)&vm[(ry*5 + k)*192] + q) = m;
                    r0 = r1; r1 = r2;
                }
            }
            __syncthreads();

            // stage 2a: pre-read boundary scalars
            float lefts[5], rights[5];
            if (act) {
                #pragma unroll
                for (int k = 0; k < 5; k++) {
                    int rr = ry*5 + k;
                    lefts[k]  = vm[rr*192 + max(4*q - 1, 0)];
                    rights[k] = vm[rr*192 + min(4*q + 4, 191)];
                }
            }
            __syncthreads();

            // stage 2b: in-place horizontal 3-max
            if (act) {
                #pragma unroll
                for (int k = 0; k < 5; k++) {
                    int rr = ry*5 + k;
                    float4 v = *((float4*)&vm[rr*192] + q);
                    float4 m;
                    m.x = fmaxf(fmaxf(lefts[k], v.x), v.y);
                    m.y = fmaxf(fmaxf(v.x,  v.y), v.z);
                    m.z = fmaxf(fmaxf(v.y,  v.z), v.w);
                    m.w = fmaxf(fmaxf(v.z,  v.w), rights[k]);
                    *((float4*)&vm[rr*192] + q) = m;
                }
            }
            __syncthreads();

            // stage 3: vertical blur (1,3,3,1); reflect pr=-1 -> 1
            if (act) {
                #pragma unroll
                for (int k = 0; k < 2; k++) {
                    int ohl = ry + k*5;
                    if (ohl < 8) {
                        int rbase = 3*ohl;
                        int r0i = (oh0 + ohl == 0) ? 2 : rbase;
                        float4 t0 = *((float4*)&vm[r0i*192]      + q);
                        float4 t1 = *((float4*)&vm[(rbase+1)*192] + q);
                        float4 t2 = *((float4*)&vm[(rbase+2)*192] + q);
                        float4 t3 = *((float4*)&vm[(rbase+3)*192] + q);
                        float4 o;
                        o.x = t0.x + 3.f*t1.x + 3.f*t2.x + t3.x;
                        o.y = t0.y + 3.f*t1.y + 3.f*t2.y + t3.y;
                        o.z = t0.z + 3.f*t1.z + 3.f*t2.z + t3.z;
                        o.w = t0.w + 3.f*t1.w + 3.f*t2.w + t3.w;
                        *((float4*)&cb[ohl*192] + q) = o;
                    }
                }
            }
            __syncthreads();

            // stage 4: horizontal blur -> xtem*64 rows in bufB (1/64 folded
            // into BN scale in phase 2)
            for (int i = tid; i < 512; i += 256) {
                int ohl = i >> 6, ow = i & 63;
                int cbase = 3*ow - 1;
                float s = cb[ohl*192 + ((cbase < 0) ? 1 : cbase)]
                        + 3.f*cb[ohl*192 + cbase+1]
                        + 3.f*cb[ohl*192 + cbase+2]
                        +      cb[ohl*192 + cbase+3];
                bufB[(oh0 + ohl)*HT + ow] = s;
            }
            __syncthreads();
        }
    }

    // ================= phase 2: stencil + BN + sigmoid =================
    {
        float* tile = bufA;   // 76x80, halo 6, col offset 8

        // zero tile, then copy xtem into center
        float4 z4 = make_float4(0.f,0.f,0.f,0.f);
        for (int i = tid; i < 6080/4; i += 256) ((float4*)tile)[i] = z4;
        __syncthreads();
        for (int i = tid; i < 1024; i += 256) {
            int r = i / 16, c4 = i % 16;
            *((float4*)&tile[(r+6)*80 + c4*4 + 8]) = ((const float4*)bufB)[i];
        }
        __syncthreads();

        int lane = tid & 31, w = tid >> 5;
        int c  = (w & 1)*32 + lane;
        int r0 = (w >> 1)*16;
        float acc[16];
        #pragma unroll
        for (int k = 0; k < 16; k++) acc[k] = 0.f;

        constexpr int LO[13] = {5,-1,-1,-1,-1,-5,-5,-5,-3,-4,-5,-6,-5};
        constexpr int HI[13] = {5, 6, 5, 4, 3, 5, 5, 5, 1, 1, 1, 1,-5};

        // weight-register formulation: weights live in regs, column values
        // streamed one at a time -> low live set (acc16 + wreg<=11 + xm)
        #pragma unroll
        for (int d = 0; d < 13; d++) {
            int cidx = c + d + 2;
            const int lo = LO[d], hi = HI[d];
            float wreg[11];
            #pragma unroll
            for (int di = lo; di <= hi; di++)
                wreg[di - lo] = wc[(di+6)*13 + d];
            #pragma unroll
            for (int m = lo+6; m <= hi+21; m++) {
                float xm = tile[(r0 + m)*80 + cidx];
                const int dlo = (lo > m-21) ? lo : (m-21);
                const int dhi = (hi < m-6)  ? hi : (m-6);
                #pragma unroll
                for (int di = dlo; di <= dhi; di++)
                    acc[m - di - 6] += wreg[di - lo] * xm;
            }
        }

        float inv0 = gamma[ch] * rsqrtf(var[ch] + 1e-5f);
        float b2   = beta[ch] - mean[ch]*inv0;
        float inv  = inv0 * (1.f/64.f);   // blur normalization folded in
        __syncthreads();  // tile reads done; bufB overwrite below is safe
        #pragma unroll
        for (int k = 0; k < 16; k++) {
            float a = acc[k]*inv + b2;
            bufB[(r0 + k)*HT + c] = 1.f / (1.f + __expf(-a));
        }
        __syncthreads();
    }

    // ================= phase 3: out = x * gate (3x upsample) =================
    {
        const float4* xp4 = (const float4*)xp;
        float4*       op4 = (float4*)(out + (size_t)plane*(HH*WW));
        #pragma unroll
        for (int bt = 0; bt < 6; ++bt) {
            float4 v[6];
            #pragma unroll
            for (int u = 0; u < 6; u++)
                v[u] = __ldg(xp4 + (bt*6 + u)*256 + tid);
            #pragma unroll
            for (int u = 0; u < 6; u++) {
                int i    = (bt*6 + u)*256 + tid;
                int rowi = i / 48;
                int j    = i - rowi*48;
                int gr   = rowi / 3;
                int q3   = j / 3;
                int rem  = j - 3*q3;
                const float* grow = bufB + gr*64 + 4*q3 + rem;
                float lo = grow[0];
                float hi = grow[1];
                float4 o;
                o.x = v[u].x * lo;
                o.y = v[u].y * ((rem == 2) ? hi : lo);
                o.z = v[u].z * ((rem >= 1) ? hi : lo);
                o.w = v[u].w * hi;
                op4[i] = o;
            }
        }
    }
}

extern "C" void kernel_launch(void* const* d_in, const int* in_sizes, int n_in,
                              void* d_out, int out_size) {
    const float* x     = (const float*)d_in[0];
    const float* wh1   = (const float*)d_in[1];
    const float* wv1   = (const float*)d_in[2];
    const float* wh2   = (const float*)d_in[3];
    const float* wv2   = (const float*)d_in[4];
    const float* gamma = (const float*)d_in[5];
    const float* beta  = (const float*)d_in[6];
    const float* mean  = (const float*)d_in[7];
    const float* var   = (const float*)d_in[8];
    float* out = (float*)d_out;

    k_mega<<<BB*CC, 256>>>(x, wh1, wv1, wh2, wv2, gamma, beta, mean, var, out);
}

// round 17
// speedup vs baseline: 4.3280x; 4.3280x over previous
#include <cuda_runtime.h>

#define BB 16
#define CC 64
#define HH 192
#define WW 192
#define HT 64   // pooled spatial size

// -------------------------------------------------------------------------
// Megakernel: one block per (b,c) plane, 256 threads.
//  phase 1: fused maxpool3x3(s1,p1) + blurpool(4x4,s3,reflect(1,2))
//           -> xtem*64 (64x64) in smem (8 chunks of 8 output rows)
//  phase 2: combined 87-tap stencil + BN(1/64 fold) + sigmoid -> gate
//           (batched rolling-window loads; all indices compile-time)
//  phase 3: out = x * gate[i/3, j/3], coalesced float4 stream (6-wide MLP)
// -------------------------------------------------------------------------
__global__ void __launch_bounds__(256) k_mega(
        const float* __restrict__ x,
        const float* __restrict__ wh1, const float* __restrict__ wv1,
        const float* __restrict__ wh2, const float* __restrict__ wv2,
        const float* __restrict__ gamma, const float* __restrict__ beta,
        const float* __restrict__ mean,  const float* __restrict__ var,
        float* __restrict__ out) {
    __shared__ float bufA[6336];   // pool: vm[25][192] @0, cb[8][192] @4800
                                   // att:  tile 76x80 @0
    __shared__ float bufB[4096];   // xtem 64x64, then gate 64x64
    __shared__ float wc[169];      // combined 13x13 stencil

    int plane = blockIdx.x;
    int ch    = plane % CC;
    int tid   = threadIdx.x;
    const float* xp = x + (size_t)plane * (HH*WW);

    // ---- build combined stencil (disjoint scatter per phase) ----
    if (tid < 169) wc[tid] = 0.f;
    __syncthreads();
    if (tid < 33) { int a = tid/3  - 5, b = tid%3  - 1; wc[(a+6)*13 + (b+6)]   += wh1[ch*33 + tid]; }
    __syncthreads();
    if (tid < 33) { int a = tid/11 - 1, b = tid%11 - 5; wc[(a+6)*13 + (b+6)]   += wv1[ch*33 + tid]; }
    __syncthreads();
    if (tid < 33) { int a = tid/3  - 5, b = tid%3  - 1; wc[(a+6)*13 + (b-a+6)] += wh2[ch*33 + tid]; }
    __syncthreads();
    if (tid < 33) { int s = tid/11 - 1, t = tid%11 - 5; wc[(s-t+6)*13 + (t+6)] += wv2[ch*33 + tid]; }

    // ================= phase 1: pool -> bufB (xtem * 64) =================
    {
        float* vm = bufA;            // [25][192]
        float* cb = bufA + 4800;     // [8][192]
        int q  = tid % 48;           // column quad
        int ry = tid / 48;           // 0..5 (active when <5)
        bool act = (tid < 240);

        for (int chunk = 0; chunk < 8; chunk++) {
            int oh0    = chunk * 8;
            int prbase = 3*oh0 - 1;

            // stage 1: rolling vertical 3-max, vm rows ry*5..ry*5+4
            if (act) {
                int base = prbase + ry*5;
                int ra = min(max(base-1, 0), 191);
                int rb = min(max(base,   0), 191);
                float4 r0 = __ldg((const float4*)(xp + (size_t)ra*WW) + q);
                float4 r1 = __ldg((const float4*)(xp + (size_t)rb*WW) + q);
                #pragma unroll
                for (int k = 0; k < 5; k++) {
                    int rc = min(max(base+k+1, 0), 191);
                    float4 r2 = __ldg((const float4*)(xp + (size_t)rc*WW) + q);
                    float4 m;
                    m.x = fmaxf(fmaxf(r0.x, r1.x), r2.x);
                    m.y = fmaxf(fmaxf(r0.y, r1.y), r2.y);
                    m.z = fmaxf(fmaxf(r0.z, r1.z), r2.z);
                    m.w = fmaxf(fmaxf(r0.w, r1.w), r2.w);
                    *((float4*)&vm[(ry*5 + k)*192] + q) = m;
                    r0 = r1; r1 = r2;
                }
            }
            __syncthreads();

            // stage 2a: pre-read boundary scalars
            float lefts[5], rights[5];
            if (act) {
                #pragma unroll
                for (int k = 0; k < 5; k++) {
                    int rr = ry*5 + k;
                    lefts[k]  = vm[rr*192 + max(4*q - 1, 0)];
                    rights[k] = vm[rr*192 + min(4*q + 4, 191)];
                }
            }
            __syncthreads();

            // stage 2b: in-place horizontal 3-max
            if (act) {
                #pragma unroll
                for (int k = 0; k < 5; k++) {
                    int rr = ry*5 + k;
                    float4 v = *((float4*)&vm[rr*192] + q);
                    float4 m;
                    m.x = fmaxf(fmaxf(lefts[k], v.x), v.y);
                    m.y = fmaxf(fmaxf(v.x,  v.y), v.z);
                    m.z = fmaxf(fmaxf(v.y,  v.z), v.w);
                    m.w = fmaxf(fmaxf(v.z,  v.w), rights[k]);
                    *((float4*)&vm[rr*192] + q) = m;
                }
            }
            __syncthreads();

            // stage 3: vertical blur (1,3,3,1); reflect pr=-1 -> 1
            if (act) {
                #pragma unroll
                for (int k = 0; k < 2; k++) {
                    int ohl = ry + k*5;
                    if (ohl < 8) {
                        int rbase = 3*ohl;
                        int r0i = (oh0 + ohl == 0) ? 2 : rbase;
                        float4 t0 = *((float4*)&vm[r0i*192]      + q);
                        float4 t1 = *((float4*)&vm[(rbase+1)*192] + q);
                        float4 t2 = *((float4*)&vm[(rbase+2)*192] + q);
                        float4 t3 = *((float4*)&vm[(rbase+3)*192] + q);
                        float4 o;
                        o.x = t0.x + 3.f*t1.x + 3.f*t2.x + t3.x;
                        o.y = t0.y + 3.f*t1.y + 3.f*t2.y + t3.y;
                        o.z = t0.z + 3.f*t1.z + 3.f*t2.z + t3.z;
                        o.w = t0.w + 3.f*t1.w + 3.f*t2.w + t3.w;
                        *((float4*)&cb[ohl*192] + q) = o;
                    }
                }
            }
            __syncthreads();

            // stage 4: horizontal blur -> xtem*64 rows in bufB (1/64 folded
            // into BN scale in phase 2)
            for (int i = tid; i < 512; i += 256) {
                int ohl = i >> 6, ow = i & 63;
                int cbase = 3*ow - 1;
                float s = cb[ohl*192 + ((cbase < 0) ? 1 : cbase)]
                        + 3.f*cb[ohl*192 + cbase+1]
                        + 3.f*cb[ohl*192 + cbase+2]
                        +      cb[ohl*192 + cbase+3];
                bufB[(oh0 + ohl)*HT + ow] = s;
            }
            __syncthreads();
        }
    }

    // ================= phase 2: stencil + BN + sigmoid =================
    {
        float* tile = bufA;   // 76x80, halo 6, col offset 8

        // zero tile, then copy xtem into center
        float4 z4 = make_float4(0.f,0.f,0.f,0.f);
        for (int i = tid; i < 6080/4; i += 256) ((float4*)tile)[i] = z4;
        __syncthreads();
        for (int i = tid; i < 1024; i += 256) {
            int r = i / 16, c4 = i % 16;
            *((float4*)&tile[(r+6)*80 + c4*4 + 8]) = ((const float4*)bufB)[i];
        }
        __syncthreads();

        int lane = tid & 31, w = tid >> 5;
        int c  = (w & 1)*32 + lane;
        int r0 = (w >> 1)*16;
        float acc[16];
        #pragma unroll
        for (int k = 0; k < 16; k++) acc[k] = 0.f;

        constexpr int LO[13] = {5,-1,-1,-1,-1,-5,-5,-5,-3,-4,-5,-6,-5};
        constexpr int HI[13] = {5, 6, 5, 4, 3, 5, 5, 5, 1, 1, 1, 1,-5};

        // rolling-window loads: batch-load first 22 column values (keeps
        // >=14 LDS in flight), run first <=7 di groups, then load the tail
        // and finish. All indices compile-time.
        #pragma unroll
        for (int d = 0; d < 13; d++) {
            const int lo = LO[d], hi = HI[d];
            int cidx = c + d + 2;
            float xr[28];
            const int mAend = (lo+27 < hi+21) ? lo+27 : hi+21;
            #pragma unroll
            for (int m = lo+6; m <= mAend; m++)
                xr[m - (lo+6)] = tile[(r0 + m)*80 + cidx];
            const int diAend = (lo+6 < hi) ? lo+6 : hi;
            #pragma unroll
            for (int di = lo; di <= diAend; di++) {
                float wv = wc[(di+6)*13 + d];
                #pragma unroll
                for (int k = 0; k < 16; k++)
                    acc[k] += wv * xr[k + di - lo];
            }
            #pragma unroll
            for (int m = lo+28; m <= hi+21; m++)
                xr[m - (lo+6)] = tile[(r0 + m)*80 + cidx];
            #pragma unroll
            for (int di = diAend+1; di <= hi; di++) {
                float wv = wc[(di+6)*13 + d];
                #pragma unroll
                for (int k = 0; k < 16; k++)
                    acc[k] += wv * xr[k + di - lo];
            }
        }

        float inv0 = gamma[ch] * rsqrtf(var[ch] + 1e-5f);
        float b2   = beta[ch] - mean[ch]*inv0;
        float inv  = inv0 * (1.f/64.f);   // blur normalization folded in
        __syncthreads();  // tile reads done; bufB overwrite below is safe
        #pragma unroll
        for (int k = 0; k < 16; k++) {
            float a = acc[k]*inv + b2;
            bufB[(r0 + k)*HT + c] = 1.f / (1.f + __expf(-a));
        }
        __syncthreads();
    }

    // ================= phase 3: out = x * gate (3x upsample) =================
    {
        const float4* xp4 = (const float4*)xp;
        float4*       op4 = (float4*)(out + (size_t)plane*(HH*WW));
        #pragma unroll
        for (int bt = 0; bt < 6; ++bt) {
            float4 v[6];
            #pragma unroll
            for (int u = 0; u < 6; u++)
                v[u] = __ldg(xp4 + (bt*6 + u)*256 + tid);
            #pragma unroll
            for (int u = 0; u < 6; u++) {
                int i    = (bt*6 + u)*256 + tid;
                int rowi = i / 48;
                int j    = i - rowi*48;
                int gr   = rowi / 3;
                int q3   = j / 3;
                int rem  = j - 3*q3;
                const float* grow = bufB + gr*64 + 4*q3 + rem;
                float lo = grow[0];
                float hi = grow[1];
                float4 o;
                o.x = v[u].x * lo;
                o.y = v[u].y * ((rem == 2) ? hi : lo);
                o.z = v[u].z * ((rem >= 1) ? hi : lo);
                o.w = v[u].w * hi;
                op4[i] = o;
            }
        }
    }
}

extern "C" void kernel_launch(void* const* d_in, const int* in_sizes, int n_in,
                              void* d_out, int out_size) {
    const float* x     = (const float*)d_in[0];
    const float* wh1   = (const float*)d_in[1];
    const float* wv1   = (const float*)d_in[2];
    const float* wh2   = (const float*)d_in[3];
    const float* wv2   = (const float*)d_in[4];
    const float* gamma = (const float*)d_in[5];
    const float* beta  = (const float*)d_in[6];
    const float* mean  = (const float*)d_in[7];
    const float* var   = (const float*)d_in[8];
    float* out = (float*)d_out;

    k_mega<<<BB*CC, 256>>>(x, wh1, wv1, wh2, wv2, gamma, beta, mean, var, out);
}